// round 4
// baseline (speedup 1.0000x reference)
#include <cuda_runtime.h>
#include <cuda_fp16.h>
#include <math.h>

#define NN 50000
#define NE 800000
#define DEPTH 4

// ---------------- scratch (static device globals; no allocation) ----------------
__device__ float  g_X  [NN*64];   // node state (fp32)
__device__ __half g_XdH[NN*64];   // dis[i]*X[i] as fp16 (gather stream, conv path)
__device__ float  g_A  [NN*64];   // aggregated features (shared by both convs)
__device__ float  g_Xn [NN*64];   // relu(conv(X))
__device__ __half g_XGH[NN*64];   // relu(gate-conv(X)) as fp16 (gather stream)
__device__ float g_dis[NN];
__device__ int g_cnt_dst[NN];
__device__ int g_cnt_src[NN];
__device__ int g_rp_dst[NN+1];
__device__ int g_rp_src[NN+1];
__device__ int g_off_dst[NN];
__device__ int g_off_src[NN];
__device__ int g_col_src[NE];   // CSR by dst: source node of each in-edge
__device__ int g_col_dst[NE];   // CSR by src: dest node of each out-edge

// ---------------- helpers ----------------
__device__ __forceinline__ uint2 f4_to_h4(float4 v) {
    __half2 h0 = __floats2half2_rn(v.x, v.y);
    __half2 h1 = __floats2half2_rn(v.z, v.w);
    uint2 r;
    r.x = *reinterpret_cast<unsigned*>(&h0);
    r.y = *reinterpret_cast<unsigned*>(&h1);
    return r;
}

// ---------------- graph preprocessing ----------------
__global__ void k_zero_counts() {
    int i = blockIdx.x * blockDim.x + threadIdx.x;
    if (i < NN) { g_cnt_dst[i] = 0; g_cnt_src[i] = 0; }
}

__global__ void k_count(const int* __restrict__ ei) {
    int i = blockIdx.x * blockDim.x + threadIdx.x;
    if (i < NE) {
        int s = ei[i], d = ei[NE + i];
        atomicAdd(&g_cnt_dst[d], 1);
        atomicAdd(&g_cnt_src[s], 1);
    }
}

__device__ void scan_phase(const int* __restrict__ cnt, int* __restrict__ rp,
                           int* __restrict__ off, bool dodis, int* part) {
    int t = threadIdx.x;
    const int CH = (NN + 1023) / 1024;
    int b = t * CH;
    int e = b + CH; if (e > NN) e = NN; if (b > NN) b = NN;
    int s = 0;
    for (int i = b; i < e; i++) s += cnt[i];
    part[t] = s;
    __syncthreads();
    for (int o = 1; o < 1024; o <<= 1) {
        int v = (t >= o) ? part[t - o] : 0;
        __syncthreads();
        part[t] += v;
        __syncthreads();
    }
    int run = (t > 0) ? part[t - 1] : 0;
    for (int i = b; i < e; i++) {
        rp[i] = run; off[i] = run; run += cnt[i];
        if (dodis) g_dis[i] = rsqrtf((float)cnt[i] + 1.0f);
    }
    if (t == 1023) rp[NN] = part[1023];
}

__global__ void k_scan2() {
    __shared__ int part[1024];
    if (blockIdx.x == 0)
        scan_phase(g_cnt_dst, g_rp_dst, g_off_dst, true, part);
    else
        scan_phase(g_cnt_src, g_rp_src, g_off_src, false, part);
}

__global__ void k_fill(const int* __restrict__ ei) {
    int i = blockIdx.x * blockDim.x + threadIdx.x;
    if (i < NE) {
        int s = ei[i], d = ei[NE + i];
        int p = atomicAdd(&g_off_dst[d], 1); g_col_src[p] = s;
        int q = atomicAdd(&g_off_src[s], 1); g_col_dst[q] = d;
    }
}

// ---------------- GEMM: A[n x K] @ W[K x 64], tile 32 rows x 64 cols ----------------
// O1 = relu(A@W1 + b1)
// DUAL:         O2h = half(relu(A@W2 + b2))
// WRITE_SCALED: Osh = half(dis[row] * O1)
template<int K, bool DUAL, bool WRITE_SCALED>
__global__ void __launch_bounds__(128) gemm_k(
    const float* __restrict__ A,
    const float* __restrict__ W1,
    const float* __restrict__ W2,
    const float* __restrict__ b1,
    const float* __restrict__ b2,
    float* __restrict__ O1,
    __half* __restrict__ O2h,
    __half* __restrict__ Osh)
{
    __shared__ float AsT[64][36];
    constexpr int NW = DUAL ? 2 : 1;
    __shared__ float Ws[NW * 64 * 64];

    int tid = threadIdx.x;            // 128 threads
    int tx = tid & 15;                // 16 col-groups of 4
    int ty = tid >> 4;                // 8 row-groups of 4
    int rowbase = blockIdx.x * 32;
    int col0 = tx * 4;

    float acc1[4][4] = {};
    float acc2[4][4] = {};

    #pragma unroll
    for (int c = 0; c < K / 64; c++) {
        #pragma unroll
        for (int it = 0; it < 4; it++) {
            int i = tid + it * 128;
            int r = i >> 4, q = i & 15;
            int row = rowbase + r;
            float4 v = make_float4(0.f, 0.f, 0.f, 0.f);
            if (row < NN)
                v = *(const float4*)&A[(size_t)row * K + c * 64 + q * 4];
            AsT[q * 4 + 0][r] = v.x; AsT[q * 4 + 1][r] = v.y;
            AsT[q * 4 + 2][r] = v.z; AsT[q * 4 + 3][r] = v.w;
        }
        #pragma unroll
        for (int i = tid; i < NW * 64 * 16; i += 128) {
            float4 v = (i < 64 * 16)
                ? ((const float4*)(W1 + c * 64 * 64))[i]
                : ((const float4*)(W2 + c * 64 * 64))[i - 64 * 16];
            ((float4*)Ws)[i] = v;
        }
        __syncthreads();

        #pragma unroll 16
        for (int kk = 0; kk < 64; kk++) {
            float4 av = *(const float4*)&AsT[kk][ty * 4];
            float4 w1 = *(const float4*)&Ws[kk * 64 + col0];
            float a[4] = {av.x, av.y, av.z, av.w};
            #pragma unroll
            for (int i = 0; i < 4; i++) {
                acc1[i][0] += a[i] * w1.x;
                acc1[i][1] += a[i] * w1.y;
                acc1[i][2] += a[i] * w1.z;
                acc1[i][3] += a[i] * w1.w;
            }
            if (DUAL) {
                float4 w2 = *(const float4*)&Ws[64 * 64 + kk * 64 + col0];
                #pragma unroll
                for (int i = 0; i < 4; i++) {
                    acc2[i][0] += a[i] * w2.x;
                    acc2[i][1] += a[i] * w2.y;
                    acc2[i][2] += a[i] * w2.z;
                    acc2[i][3] += a[i] * w2.w;
                }
            }
        }
        __syncthreads();
    }

    float4 bb1 = *(const float4*)&b1[col0];
    float4 bb2 = DUAL ? *(const float4*)&b2[col0] : make_float4(0.f, 0.f, 0.f, 0.f);

    #pragma unroll
    for (int i = 0; i < 4; i++) {
        int row = rowbase + ty * 4 + i;
        if (row >= NN) break;
        float4 o;
        o.x = fmaxf(acc1[i][0] + bb1.x, 0.f);
        o.y = fmaxf(acc1[i][1] + bb1.y, 0.f);
        o.z = fmaxf(acc1[i][2] + bb1.z, 0.f);
        o.w = fmaxf(acc1[i][3] + bb1.w, 0.f);
        *(float4*)&O1[(size_t)row * 64 + col0] = o;
        if (WRITE_SCALED) {
            float s = g_dis[row];
            float4 os = make_float4(s * o.x, s * o.y, s * o.z, s * o.w);
            *(uint2*)&Osh[(size_t)row * 64 + col0] = f4_to_h4(os);
        }
        if (DUAL) {
            float4 o2;
            o2.x = fmaxf(acc2[i][0] + bb2.x, 0.f);
            o2.y = fmaxf(acc2[i][1] + bb2.y, 0.f);
            o2.z = fmaxf(acc2[i][2] + bb2.z, 0.f);
            o2.w = fmaxf(acc2[i][3] + bb2.w, 0.f);
            *(uint2*)&O2h[(size_t)row * 64 + col0] = f4_to_h4(o2);
        }
    }
}

// ---------------- shared aggregation over in-edges (CSR by dst) ----------------
// A[d] = dis[d] * ( XdH[d] + sum_{s->d} XdH[s] )
// One warp per node; lane l handles features [2l, 2l+1] (half2 per edge)
__global__ void __launch_bounds__(256) k_agg()
{
    int g = (blockIdx.x * blockDim.x + threadIdx.x) >> 5;
    int l = threadIdx.x & 31;
    if (g >= NN) return;
    int o = l * 2;

    float2 a = __half22float2(*(const __half2*)&g_XdH[(size_t)g * 64 + o]); // self-loop

    int b = g_rp_dst[g], e = g_rp_dst[g + 1];
    int j = b;
    for (; j + 4 <= e; j += 4) {
        int s0 = g_col_src[j + 0];
        int s1 = g_col_src[j + 1];
        int s2 = g_col_src[j + 2];
        int s3 = g_col_src[j + 3];
        float2 v0 = __half22float2(*(const __half2*)&g_XdH[(size_t)s0 * 64 + o]);
        float2 v1 = __half22float2(*(const __half2*)&g_XdH[(size_t)s1 * 64 + o]);
        float2 v2 = __half22float2(*(const __half2*)&g_XdH[(size_t)s2 * 64 + o]);
        float2 v3 = __half22float2(*(const __half2*)&g_XdH[(size_t)s3 * 64 + o]);
        a.x += (v0.x + v1.x) + (v2.x + v3.x);
        a.y += (v0.y + v1.y) + (v2.y + v3.y);
    }
    for (; j < e; j++) {
        int s = g_col_src[j];
        float2 v = __half22float2(*(const __half2*)&g_XdH[(size_t)s * 64 + o]);
        a.x += v.x; a.y += v.y;
    }
    float d = g_dis[g];
    float2 r = make_float2(d * a.x, d * a.y);
    *(float2*)&g_A[(size_t)g * 64 + o] = r;
}

// ---------------- gate + state update (CSR by src) ----------------
// tau = tanh( sum_out (XG[s]-XG[d])^2 / max(outdeg,1) )
// X = X + tau*(Xn - X);  XdH = half(dis*X)
__global__ void __launch_bounds__(256) k_gate()
{
    int g = (blockIdx.x * blockDim.x + threadIdx.x) >> 5;
    int l = threadIdx.x & 31;
    if (g >= NN) return;
    int o = l * 2;

    float2 xs = __half22float2(*(const __half2*)&g_XGH[(size_t)g * 64 + o]);
    float2 s = make_float2(0.f, 0.f);
    int b = g_rp_src[g], e = g_rp_src[g + 1];
    int j = b;
    for (; j + 4 <= e; j += 4) {
        int d0 = g_col_dst[j + 0];
        int d1 = g_col_dst[j + 1];
        int d2 = g_col_dst[j + 2];
        int d3 = g_col_dst[j + 3];
        float2 v0 = __half22float2(*(const __half2*)&g_XGH[(size_t)d0 * 64 + o]);
        float2 v1 = __half22float2(*(const __half2*)&g_XGH[(size_t)d1 * 64 + o]);
        float2 v2 = __half22float2(*(const __half2*)&g_XGH[(size_t)d2 * 64 + o]);
        float2 v3 = __half22float2(*(const __half2*)&g_XGH[(size_t)d3 * 64 + o]);
        float t;
        t = xs.x - v0.x; s.x += t * t;  t = xs.y - v0.y; s.y += t * t;
        t = xs.x - v1.x; s.x += t * t;  t = xs.y - v1.y; s.y += t * t;
        t = xs.x - v2.x; s.x += t * t;  t = xs.y - v2.y; s.y += t * t;
        t = xs.x - v3.x; s.x += t * t;  t = xs.y - v3.y; s.y += t * t;
    }
    for (; j < e; j++) {
        int d = g_col_dst[j];
        float2 v = __half22float2(*(const __half2*)&g_XGH[(size_t)d * 64 + o]);
        float t;
        t = xs.x - v.x; s.x += t * t;  t = xs.y - v.y; s.y += t * t;
    }
    float inv = 1.0f / fmaxf((float)(e - b), 1.f);
    float2 tau = make_float2(tanhf(s.x * inv), tanhf(s.y * inv));

    float2 xo = *(const float2*)&g_X [(size_t)g * 64 + o];
    float2 xn = *(const float2*)&g_Xn[(size_t)g * 64 + o];
    float2 r;
    r.x = xo.x + tau.x * (xn.x - xo.x);
    r.y = xo.y + tau.y * (xn.y - xo.y);
    *(float2*)&g_X[(size_t)g * 64 + o] = r;
    float di = g_dis[g];
    *(__half2*)&g_XdH[(size_t)g * 64 + o] = __floats2half2_rn(di * r.x, di * r.y);
}

// ---------------- launch ----------------
extern "C" void kernel_launch(void* const* d_in, const int* in_sizes, int n_in,
                              void* d_out, int out_size)
{
    const float* x      = (const float*)d_in[0];
    const int*   ei     = (const int*)  d_in[1];
    const float* enc_w  = (const float*)d_in[2];
    const float* enc_b  = (const float*)d_in[3];
    const float* conv_w = (const float*)d_in[4];
    const float* conv_b = (const float*)d_in[5];
    const float* gg_w   = (const float*)d_in[6];
    const float* gg_b   = (const float*)d_in[7];
    const float* dec_w  = (const float*)d_in[8];
    const float* dec_b  = (const float*)d_in[9];
    float* out = (float*)d_out;

    float *pX, *pA, *pXn;
    __half *pXdH, *pXGH;
    cudaGetSymbolAddress((void**)&pX,   g_X);
    cudaGetSymbolAddress((void**)&pXdH, g_XdH);
    cudaGetSymbolAddress((void**)&pA,   g_A);
    cudaGetSymbolAddress((void**)&pXn,  g_Xn);
    cudaGetSymbolAddress((void**)&pXGH, g_XGH);

    // graph preprocessing (per-launch; deterministic)
    k_zero_counts<<<(NN + 255) / 256, 256>>>();
    k_count<<<(NE + 255) / 256, 256>>>(ei);
    k_scan2<<<2, 1024>>>();
    k_fill<<<(NE + 255) / 256, 256>>>(ei);

    const int GEMM_BLOCKS = (NN + 31) / 32;
    const int NODE_BLOCKS = (NN * 32 + 255) / 256;   // warp per node

    // encoder: X = relu(x @ enc_w + enc_b); XdH = half(dis*X)
    gemm_k<256, false, true><<<GEMM_BLOCKS, 128>>>(
        x, enc_w, nullptr, enc_b, nullptr, pX, nullptr, pXdH);

    for (int it = 0; it < DEPTH; it++) {
        k_agg<<<NODE_BLOCKS, 256>>>();
        gemm_k<64, true, false><<<GEMM_BLOCKS, 128>>>(
            pA, conv_w, gg_w, conv_b, gg_b, pXn, pXGH, nullptr);
        k_gate<<<NODE_BLOCKS, 256>>>();
    }

    // decoder: out = relu(X @ dec_w + dec_b)
    gemm_k<64, false, false><<<GEMM_BLOCKS, 128>>>(
        pX, dec_w, nullptr, dec_b, nullptr, out, nullptr, nullptr);
}

// round 5
// speedup vs baseline: 1.2160x; 1.2160x over previous
#include <cuda_runtime.h>
#include <cuda_fp16.h>
#include <math.h>

#define NN 50000
#define NE 800000
#define DEPTH 4

// ---------------- scratch (static device globals; no allocation) ----------------
__device__ float  g_X  [NN*64];   // node state (fp32)
__device__ __half g_XdH[NN*64];   // dis[i]*X[i] as fp16 (gather stream)
__device__ __half g_AH [NN*64];   // aggregated features as fp16 (MMA input)
__device__ float  g_Xn [NN*64];   // relu(conv(X))
__device__ __half g_XGH[NN*64];   // relu(gate-conv(X)) as fp16 (gather stream)
__device__ __half g_Wt1[64*64];   // conv_w transposed fp16: [n][k]
__device__ __half g_Wt2[64*64];   // gg_w transposed fp16: [n][k]
__device__ float g_dis[NN];
__device__ int g_cnt_dst[NN];
__device__ int g_cnt_src[NN];
__device__ int g_rp_dst[NN+1];
__device__ int g_rp_src[NN+1];
__device__ int g_off_dst[NN];
__device__ int g_off_src[NN];
__device__ int g_col_src[NE];   // CSR by dst
__device__ int g_col_dst[NE];   // CSR by src

// ---------------- helpers ----------------
__device__ __forceinline__ float4 h4_to_f4(uint2 raw) {
    __half2 h0 = *reinterpret_cast<__half2*>(&raw.x);
    __half2 h1 = *reinterpret_cast<__half2*>(&raw.y);
    float2 f0 = __half22float2(h0);
    float2 f1 = __half22float2(h1);
    return make_float4(f0.x, f0.y, f1.x, f1.y);
}
__device__ __forceinline__ uint2 f4_to_h4(float4 v) {
    __half2 h0 = __floats2half2_rn(v.x, v.y);
    __half2 h1 = __floats2half2_rn(v.z, v.w);
    uint2 r;
    r.x = *reinterpret_cast<unsigned*>(&h0);
    r.y = *reinterpret_cast<unsigned*>(&h1);
    return r;
}
__device__ __forceinline__ void mma16816(float c[4],
    unsigned a0, unsigned a1, unsigned a2, unsigned a3,
    unsigned b0, unsigned b1)
{
    asm volatile(
        "mma.sync.aligned.m16n8k16.row.col.f32.f16.f16.f32 "
        "{%0,%1,%2,%3}, {%4,%5,%6,%7}, {%8,%9}, {%0,%1,%2,%3};"
        : "+f"(c[0]), "+f"(c[1]), "+f"(c[2]), "+f"(c[3])
        : "r"(a0), "r"(a1), "r"(a2), "r"(a3), "r"(b0), "r"(b1));
}

// ---------------- graph preprocessing ----------------
__global__ void k_zero_counts() {
    int i = blockIdx.x * blockDim.x + threadIdx.x;
    if (i < NN) { g_cnt_dst[i] = 0; g_cnt_src[i] = 0; }
}

__global__ void k_count(const int* __restrict__ ei) {
    int i = blockIdx.x * blockDim.x + threadIdx.x;
    if (i < NE) {
        int s = ei[i], d = ei[NE + i];
        atomicAdd(&g_cnt_dst[d], 1);
        atomicAdd(&g_cnt_src[s], 1);
    }
}

__device__ void scan_phase(const int* __restrict__ cnt, int* __restrict__ rp,
                           int* __restrict__ off, bool dodis, int* part) {
    int t = threadIdx.x;
    const int CH = (NN + 1023) / 1024;
    int b = t * CH;
    int e = b + CH; if (e > NN) e = NN; if (b > NN) b = NN;
    int s = 0;
    for (int i = b; i < e; i++) s += cnt[i];
    part[t] = s;
    __syncthreads();
    for (int o = 1; o < 1024; o <<= 1) {
        int v = (t >= o) ? part[t - o] : 0;
        __syncthreads();
        part[t] += v;
        __syncthreads();
    }
    int run = (t > 0) ? part[t - 1] : 0;
    for (int i = b; i < e; i++) {
        rp[i] = run; off[i] = run; run += cnt[i];
        if (dodis) g_dis[i] = rsqrtf((float)cnt[i] + 1.0f);
    }
    if (t == 1023) rp[NN] = part[1023];
}

__global__ void k_scan2() {
    __shared__ int part[1024];
    if (blockIdx.x == 0)
        scan_phase(g_cnt_dst, g_rp_dst, g_off_dst, true, part);
    else
        scan_phase(g_cnt_src, g_rp_src, g_off_src, false, part);
}

__global__ void k_fill(const int* __restrict__ ei) {
    int i = blockIdx.x * blockDim.x + threadIdx.x;
    if (i < NE) {
        int s = ei[i], d = ei[NE + i];
        int p = atomicAdd(&g_off_dst[d], 1); g_col_src[p] = s;
        int q = atomicAdd(&g_off_src[s], 1); g_col_dst[q] = d;
    }
}

// ---------------- weight convert: fp32 [k][n] -> fp16 transposed [n][k] ----------------
__global__ void k_wconv(const float* __restrict__ w1, const float* __restrict__ w2) {
    int i = blockIdx.x * blockDim.x + threadIdx.x;
    if (i < 4096) {
        int k = i >> 6, n = i & 63;
        g_Wt1[n * 64 + k] = __float2half(w1[i]);
        g_Wt2[n * 64 + k] = __float2half(w2[i]);
    }
}

// ---------------- scalar GEMM (encoder/decoder, fp32): A[n x K] @ W[K x 64] ----------------
// O1 = relu(A@W1 + b1);  WRITE_SCALED: Osh = half(dis[row] * O1)
template<int K, bool WRITE_SCALED>
__global__ void __launch_bounds__(128) gemm_k(
    const float* __restrict__ A,
    const float* __restrict__ W1,
    const float* __restrict__ b1,
    float* __restrict__ O1,
    __half* __restrict__ Osh)
{
    __shared__ float AsT[64][36];
    __shared__ float Ws[64 * 64];

    int tid = threadIdx.x;
    int tx = tid & 15;
    int ty = tid >> 4;
    int rowbase = blockIdx.x * 32;
    int col0 = tx * 4;

    float acc1[4][4] = {};

    #pragma unroll
    for (int c = 0; c < K / 64; c++) {
        #pragma unroll
        for (int it = 0; it < 4; it++) {
            int i = tid + it * 128;
            int r = i >> 4, q = i & 15;
            int row = rowbase + r;
            float4 v = make_float4(0.f, 0.f, 0.f, 0.f);
            if (row < NN)
                v = *(const float4*)&A[(size_t)row * K + c * 64 + q * 4];
            AsT[q * 4 + 0][r] = v.x; AsT[q * 4 + 1][r] = v.y;
            AsT[q * 4 + 2][r] = v.z; AsT[q * 4 + 3][r] = v.w;
        }
        #pragma unroll
        for (int i = tid; i < 64 * 16; i += 128)
            ((float4*)Ws)[i] = ((const float4*)(W1 + c * 64 * 64))[i];
        __syncthreads();

        #pragma unroll 16
        for (int kk = 0; kk < 64; kk++) {
            float4 av = *(const float4*)&AsT[kk][ty * 4];
            float4 w1 = *(const float4*)&Ws[kk * 64 + col0];
            float a[4] = {av.x, av.y, av.z, av.w};
            #pragma unroll
            for (int i = 0; i < 4; i++) {
                acc1[i][0] += a[i] * w1.x;
                acc1[i][1] += a[i] * w1.y;
                acc1[i][2] += a[i] * w1.z;
                acc1[i][3] += a[i] * w1.w;
            }
        }
        __syncthreads();
    }

    float4 bb1 = *(const float4*)&b1[col0];
    #pragma unroll
    for (int i = 0; i < 4; i++) {
        int row = rowbase + ty * 4 + i;
        if (row >= NN) break;
        float4 o;
        o.x = fmaxf(acc1[i][0] + bb1.x, 0.f);
        o.y = fmaxf(acc1[i][1] + bb1.y, 0.f);
        o.z = fmaxf(acc1[i][2] + bb1.z, 0.f);
        o.w = fmaxf(acc1[i][3] + bb1.w, 0.f);
        *(float4*)&O1[(size_t)row * 64 + col0] = o;
        if (WRITE_SCALED) {
            float s = g_dis[row];
            float4 os = make_float4(s * o.x, s * o.y, s * o.z, s * o.w);
            *(uint2*)&Osh[(size_t)row * 64 + col0] = f4_to_h4(os);
        }
    }
}

// ---------------- tensor-core dual GEMM: AH[n x 64] fp16 @ {Wt1,Wt2} ----------------
// Xn = relu(AH@W1 + b1) fp32;  XGH = half(relu(AH@W2 + b2))
// block = 128 thr (4 warps), 64 rows per block, warp = 16 rows x 64 cols, K=64
__global__ void __launch_bounds__(128) k_mma_dual(
    const float* __restrict__ b1v, const float* __restrict__ b2v)
{
    __shared__ __half As [64 * 72];
    __shared__ __half B1s[64 * 72];
    __shared__ __half B2s[64 * 72];

    int tid = threadIdx.x;
    int rowbase = blockIdx.x * 64;

    // load A tile (64 x 64 fp16), padded stride 72 halves
    #pragma unroll
    for (int it = 0; it < 8; it++) {
        int i = tid + it * 128;           // 0..1023 uint2
        int r = i >> 4;
        int c4 = (i & 15) * 4;
        int row = rowbase + r;
        uint2 v = make_uint2(0u, 0u);
        if (row < NN) v = *(const uint2*)&g_AH[(size_t)row * 64 + c4];
        *(uint2*)&As[r * 72 + c4] = v;
    }
    // load both weight tiles
    #pragma unroll
    for (int it = 0; it < 8; it++) {
        int i = tid + it * 128;
        int n = i >> 4;
        int c4 = (i & 15) * 4;
        *(uint2*)&B1s[n * 72 + c4] = *(const uint2*)&g_Wt1[n * 64 + c4];
        *(uint2*)&B2s[n * 72 + c4] = *(const uint2*)&g_Wt2[n * 64 + c4];
    }
    __syncthreads();

    int w = tid >> 5, lane = tid & 31;
    int g = lane >> 2, tig = lane & 3;
    int m0 = w * 16;

    float c1[8][4], c2[8][4];
    #pragma unroll
    for (int nc = 0; nc < 8; nc++)
        #pragma unroll
        for (int q = 0; q < 4; q++) { c1[nc][q] = 0.f; c2[nc][q] = 0.f; }

    #pragma unroll
    for (int kc = 0; kc < 4; kc++) {
        int k0 = kc * 16 + tig * 2;
        unsigned a0 = *(const unsigned*)&As[(m0 + g    ) * 72 + k0];
        unsigned a1 = *(const unsigned*)&As[(m0 + g + 8) * 72 + k0];
        unsigned a2 = *(const unsigned*)&As[(m0 + g    ) * 72 + k0 + 8];
        unsigned a3 = *(const unsigned*)&As[(m0 + g + 8) * 72 + k0 + 8];
        #pragma unroll
        for (int nc = 0; nc < 8; nc++) {
            int nr = nc * 8 + g;
            unsigned p0 = *(const unsigned*)&B1s[nr * 72 + k0];
            unsigned p1 = *(const unsigned*)&B1s[nr * 72 + k0 + 8];
            mma16816(c1[nc], a0, a1, a2, a3, p0, p1);
            unsigned q0 = *(const unsigned*)&B2s[nr * 72 + k0];
            unsigned q1 = *(const unsigned*)&B2s[nr * 72 + k0 + 8];
            mma16816(c2[nc], a0, a1, a2, a3, q0, q1);
        }
    }

    int row_lo = rowbase + m0 + g;
    int row_hi = row_lo + 8;
    #pragma unroll
    for (int nc = 0; nc < 8; nc++) {
        int col = nc * 8 + tig * 2;
        float2 bb1 = *(const float2*)&b1v[col];
        float2 bb2 = *(const float2*)&b2v[col];
        if (row_lo < NN) {
            float2 o;
            o.x = fmaxf(c1[nc][0] + bb1.x, 0.f);
            o.y = fmaxf(c1[nc][1] + bb1.y, 0.f);
            *(float2*)&g_Xn[(size_t)row_lo * 64 + col] = o;
            *(__half2*)&g_XGH[(size_t)row_lo * 64 + col] =
                __floats2half2_rn(fmaxf(c2[nc][0] + bb2.x, 0.f),
                                  fmaxf(c2[nc][1] + bb2.y, 0.f));
        }
        if (row_hi < NN) {
            float2 o;
            o.x = fmaxf(c1[nc][2] + bb1.x, 0.f);
            o.y = fmaxf(c1[nc][3] + bb1.y, 0.f);
            *(float2*)&g_Xn[(size_t)row_hi * 64 + col] = o;
            *(__half2*)&g_XGH[(size_t)row_hi * 64 + col] =
                __floats2half2_rn(fmaxf(c2[nc][2] + bb2.x, 0.f),
                                  fmaxf(c2[nc][3] + bb2.y, 0.f));
        }
    }
}

// ---------------- shared aggregation over in-edges (CSR by dst) — R3 form ----------------
// AH[d] = half( dis[d] * ( XdH[d] + sum_{s->d} XdH[s] ) )
// 16 lanes per node, 4 features (8B fp16) per lane; 4-way pipelined edge loop
__global__ void __launch_bounds__(256) k_agg()
{
    int g = (blockIdx.x * blockDim.x + threadIdx.x) >> 4;
    int l = threadIdx.x & 15;
    if (g >= NN) return;
    int o = l * 4;

    float4 a = h4_to_f4(*(const uint2*)&g_XdH[(size_t)g * 64 + o]);  // self-loop

    int b = g_rp_dst[g], e = g_rp_dst[g + 1];
    int j = b;
    for (; j + 4 <= e; j += 4) {
        int s0 = g_col_src[j + 0];
        int s1 = g_col_src[j + 1];
        int s2 = g_col_src[j + 2];
        int s3 = g_col_src[j + 3];
        uint2 r0 = *(const uint2*)&g_XdH[(size_t)s0 * 64 + o];
        uint2 r1 = *(const uint2*)&g_XdH[(size_t)s1 * 64 + o];
        uint2 r2 = *(const uint2*)&g_XdH[(size_t)s2 * 64 + o];
        uint2 r3 = *(const uint2*)&g_XdH[(size_t)s3 * 64 + o];
        float4 v0 = h4_to_f4(r0), v1 = h4_to_f4(r1);
        float4 v2 = h4_to_f4(r2), v3 = h4_to_f4(r3);
        a.x += (v0.x + v1.x) + (v2.x + v3.x);
        a.y += (v0.y + v1.y) + (v2.y + v3.y);
        a.z += (v0.z + v1.z) + (v2.z + v3.z);
        a.w += (v0.w + v1.w) + (v2.w + v3.w);
    }
    for (; j < e; j++) {
        int s = g_col_src[j];
        float4 v = h4_to_f4(*(const uint2*)&g_XdH[(size_t)s * 64 + o]);
        a.x += v.x; a.y += v.y; a.z += v.z; a.w += v.w;
    }
    float d = g_dis[g];
    float4 r = make_float4(d * a.x, d * a.y, d * a.z, d * a.w);
    *(uint2*)&g_AH[(size_t)g * 64 + o] = f4_to_h4(r);
}

// ---------------- gate + state update (CSR by src) — R3 form ----------------
__global__ void __launch_bounds__(256) k_gate()
{
    int g = (blockIdx.x * blockDim.x + threadIdx.x) >> 4;
    int l = threadIdx.x & 15;
    if (g >= NN) return;
    int o = l * 4;

    float4 xs = h4_to_f4(*(const uint2*)&g_XGH[(size_t)g * 64 + o]);
    float4 s = make_float4(0.f, 0.f, 0.f, 0.f);
    int b = g_rp_src[g], e = g_rp_src[g + 1];
    int j = b;
    for (; j + 4 <= e; j += 4) {
        int d0 = g_col_dst[j + 0];
        int d1 = g_col_dst[j + 1];
        int d2 = g_col_dst[j + 2];
        int d3 = g_col_dst[j + 3];
        uint2 r0 = *(const uint2*)&g_XGH[(size_t)d0 * 64 + o];
        uint2 r1 = *(const uint2*)&g_XGH[(size_t)d1 * 64 + o];
        uint2 r2 = *(const uint2*)&g_XGH[(size_t)d2 * 64 + o];
        uint2 r3 = *(const uint2*)&g_XGH[(size_t)d3 * 64 + o];
        float4 v0 = h4_to_f4(r0), v1 = h4_to_f4(r1);
        float4 v2 = h4_to_f4(r2), v3 = h4_to_f4(r3);
        float t;
        t = xs.x - v0.x; s.x += t * t;  t = xs.y - v0.y; s.y += t * t;
        t = xs.z - v0.z; s.z += t * t;  t = xs.w - v0.w; s.w += t * t;
        t = xs.x - v1.x; s.x += t * t;  t = xs.y - v1.y; s.y += t * t;
        t = xs.z - v1.z; s.z += t * t;  t = xs.w - v1.w; s.w += t * t;
        t = xs.x - v2.x; s.x += t * t;  t = xs.y - v2.y; s.y += t * t;
        t = xs.z - v2.z; s.z += t * t;  t = xs.w - v2.w; s.w += t * t;
        t = xs.x - v3.x; s.x += t * t;  t = xs.y - v3.y; s.y += t * t;
        t = xs.z - v3.z; s.z += t * t;  t = xs.w - v3.w; s.w += t * t;
    }
    for (; j < e; j++) {
        int d = g_col_dst[j];
        float4 v = h4_to_f4(*(const uint2*)&g_XGH[(size_t)d * 64 + o]);
        float t;
        t = xs.x - v.x; s.x += t * t;  t = xs.y - v.y; s.y += t * t;
        t = xs.z - v.z; s.z += t * t;  t = xs.w - v.w; s.w += t * t;
    }
    float inv = 1.0f / fmaxf((float)(e - b), 1.f);
    float4 tau;
    tau.x = tanhf(s.x * inv); tau.y = tanhf(s.y * inv);
    tau.z = tanhf(s.z * inv); tau.w = tanhf(s.w * inv);

    float4 xo = *(const float4*)&g_X [(size_t)g * 64 + o];
    float4 xn = *(const float4*)&g_Xn[(size_t)g * 64 + o];
    float4 r;
    r.x = xo.x + tau.x * (xn.x - xo.x);
    r.y = xo.y + tau.y * (xn.y - xo.y);
    r.z = xo.z + tau.z * (xn.z - xo.z);
    r.w = xo.w + tau.w * (xn.w - xo.w);
    *(float4*)&g_X[(size_t)g * 64 + o] = r;
    float di = g_dis[g];
    float4 rd = make_float4(di * r.x, di * r.y, di * r.z, di * r.w);
    *(uint2*)&g_XdH[(size_t)g * 64 + o] = f4_to_h4(rd);
}

// ---------------- launch ----------------
extern "C" void kernel_launch(void* const* d_in, const int* in_sizes, int n_in,
                              void* d_out, int out_size)
{
    const float* x      = (const float*)d_in[0];
    const int*   ei     = (const int*)  d_in[1];
    const float* enc_w  = (const float*)d_in[2];
    const float* enc_b  = (const float*)d_in[3];
    const float* conv_w = (const float*)d_in[4];
    const float* conv_b = (const float*)d_in[5];
    const float* gg_w   = (const float*)d_in[6];
    const float* gg_b   = (const float*)d_in[7];
    const float* dec_w  = (const float*)d_in[8];
    const float* dec_b  = (const float*)d_in[9];
    float* out = (float*)d_out;

    float *pX, *pXn;
    __half *pXdH;
    cudaGetSymbolAddress((void**)&pX,   g_X);
    cudaGetSymbolAddress((void**)&pXdH, g_XdH);
    cudaGetSymbolAddress((void**)&pXn,  g_Xn);

    // graph preprocessing + weight conversion
    k_zero_counts<<<(NN + 255) / 256, 256>>>();
    k_wconv<<<16, 256>>>(conv_w, gg_w);
    k_count<<<(NE + 255) / 256, 256>>>(ei);
    k_scan2<<<2, 1024>>>();
    k_fill<<<(NE + 255) / 256, 256>>>(ei);

    const int GEMM_BLOCKS = (NN + 31) / 32;
    const int MMA_BLOCKS  = (NN + 63) / 64;
    const int NODE_BLOCKS = (NN * 16 + 255) / 256;

    // encoder: X = relu(x @ enc_w + enc_b); XdH = half(dis*X)
    gemm_k<256, true><<<GEMM_BLOCKS, 128>>>(x, enc_w, enc_b, pX, pXdH);

    for (int it = 0; it < DEPTH; it++) {
        k_agg<<<NODE_BLOCKS, 256>>>();
        k_mma_dual<<<MMA_BLOCKS, 128>>>(conv_b, gg_b);
        k_gate<<<NODE_BLOCKS, 256>>>();
    }

    // decoder: out = relu(X @ dec_w + dec_b)
    gemm_k<64, false><<<GEMM_BLOCKS, 128>>>(pX, dec_w, dec_b, out, nullptr);
}

// round 6
// speedup vs baseline: 1.6305x; 1.3408x over previous
#include <cuda_runtime.h>
#include <cuda_fp16.h>
#include <math.h>

#define NN 50000
#define NE 800000
#define DEPTH 4
#define NBLK 196   // (NN + 255) / 256

// ---------------- scratch (static device globals; no allocation) ----------------
__device__ float  g_X  [NN*64];   // node state (fp32)
__device__ __half g_XdH[NN*64];   // dis[i]*X[i] as fp16 (gather stream)
__device__ __half g_AH [NN*64];   // aggregated features as fp16 (MMA input)
__device__ float  g_Xn [NN*64];   // relu(conv(X))
__device__ __half g_XGH[NN*64];   // relu(gate-conv(X)) as fp16 (gather stream)
__device__ __half g_Wt1[64*64];   // conv_w transposed fp16: [n][k]
__device__ __half g_Wt2[64*64];   // gg_w transposed fp16: [n][k]
__device__ float g_dis[NN];
__device__ int g_cnt_dst[NN];
__device__ int g_cnt_src[NN];
__device__ int g_rp_dst[NN+1];
__device__ int g_rp_src[NN+1];
__device__ int g_off_dst[NN];
__device__ int g_off_src[NN];
__device__ int g_col_src[NE];   // CSR by dst
__device__ int g_col_dst[NE];   // CSR by src
__device__ int g_bsum[2][NBLK];
__device__ int g_bpre[2][NBLK];

// ---------------- helpers ----------------
__device__ __forceinline__ float4 h4_to_f4(uint2 raw) {
    __half2 h0 = *reinterpret_cast<__half2*>(&raw.x);
    __half2 h1 = *reinterpret_cast<__half2*>(&raw.y);
    float2 f0 = __half22float2(h0);
    float2 f1 = __half22float2(h1);
    return make_float4(f0.x, f0.y, f1.x, f1.y);
}
__device__ __forceinline__ uint2 f4_to_h4(float4 v) {
    __half2 h0 = __floats2half2_rn(v.x, v.y);
    __half2 h1 = __floats2half2_rn(v.z, v.w);
    uint2 r;
    r.x = *reinterpret_cast<unsigned*>(&h0);
    r.y = *reinterpret_cast<unsigned*>(&h1);
    return r;
}
__device__ __forceinline__ void mma16816(float c[4],
    unsigned a0, unsigned a1, unsigned a2, unsigned a3,
    unsigned b0, unsigned b1)
{
    asm volatile(
        "mma.sync.aligned.m16n8k16.row.col.f32.f16.f16.f32 "
        "{%0,%1,%2,%3}, {%4,%5,%6,%7}, {%8,%9}, {%0,%1,%2,%3};"
        : "+f"(c[0]), "+f"(c[1]), "+f"(c[2]), "+f"(c[3])
        : "r"(a0), "r"(a1), "r"(a2), "r"(a3), "r"(b0), "r"(b1));
}

// inclusive block scan, 256 threads (8 warps)
__device__ __forceinline__ int block_incl_scan(int v, int* warpsums) {
    int lane = threadIdx.x & 31, wid = threadIdx.x >> 5;
    #pragma unroll
    for (int o = 1; o < 32; o <<= 1) {
        int u = __shfl_up_sync(0xffffffffu, v, o);
        if (lane >= o) v += u;
    }
    if (lane == 31) warpsums[wid] = v;
    __syncthreads();
    if (wid == 0) {
        int s = (lane < 8) ? warpsums[lane] : 0;
        #pragma unroll
        for (int o = 1; o < 8; o <<= 1) {
            int u = __shfl_up_sync(0xffffffffu, s, o);
            if (lane >= o) s += u;
        }
        if (lane < 8) warpsums[lane] = s;
    }
    __syncthreads();
    if (wid > 0) v += warpsums[wid - 1];
    return v;
}

// ---------------- graph preprocessing ----------------
__global__ void k_zero_counts() {
    int i = blockIdx.x * blockDim.x + threadIdx.x;
    if (i < NN) { g_cnt_dst[i] = 0; g_cnt_src[i] = 0; }
}

__global__ void k_count(const int* __restrict__ ei) {
    int i = blockIdx.x * blockDim.x + threadIdx.x;
    if (i < NE) {
        int s = ei[i], d = ei[NE + i];
        atomicAdd(&g_cnt_dst[d], 1);
        atomicAdd(&g_cnt_src[s], 1);
    }
}

__global__ void __launch_bounds__(256) k_blocksum() {
    __shared__ int warpsums[8];
    int arr = blockIdx.y;
    const int* cnt = arr ? g_cnt_src : g_cnt_dst;
    int i = blockIdx.x * 256 + threadIdx.x;
    int v = (i < NN) ? cnt[i] : 0;
    int inc = block_incl_scan(v, warpsums);
    if (threadIdx.x == 255) g_bsum[arr][blockIdx.x] = inc;
}

__global__ void __launch_bounds__(256) k_scan_bsum() {
    __shared__ int warpsums[8];
    int arr = blockIdx.x;
    int t = threadIdx.x;
    int v = (t < NBLK) ? g_bsum[arr][t] : 0;
    int inc = block_incl_scan(v, warpsums);
    if (t < NBLK) g_bpre[arr][t] = inc - v;   // exclusive
}

__global__ void __launch_bounds__(256) k_scatter() {
    __shared__ int warpsums[8];
    int arr = blockIdx.y;
    const int* cnt = arr ? g_cnt_src : g_cnt_dst;
    int* rp  = arr ? g_rp_src  : g_rp_dst;
    int* off = arr ? g_off_src : g_off_dst;
    int i = blockIdx.x * 256 + threadIdx.x;
    int v = (i < NN) ? cnt[i] : 0;
    int inc = block_incl_scan(v, warpsums);
    int base = g_bpre[arr][blockIdx.x];
    if (i < NN) {
        int ex = base + inc - v;
        rp[i] = ex; off[i] = ex;
        if (arr == 0) g_dis[i] = rsqrtf((float)v + 1.0f);
        if (i == NN - 1) rp[NN] = base + inc;
    }
}

__global__ void k_fill(const int* __restrict__ ei) {
    int i = blockIdx.x * blockDim.x + threadIdx.x;
    if (i < NE) {
        int s = ei[i], d = ei[NE + i];
        int p = atomicAdd(&g_off_dst[d], 1); g_col_src[p] = s;
        int q = atomicAdd(&g_off_src[s], 1); g_col_dst[q] = d;
    }
}

// ---------------- weight convert: fp32 [k][n] -> fp16 transposed [n][k] ----------------
__global__ void k_wconv(const float* __restrict__ w1, const float* __restrict__ w2) {
    int i = blockIdx.x * blockDim.x + threadIdx.x;
    if (i < 4096) {
        int k = i >> 6, n = i & 63;
        g_Wt1[n * 64 + k] = __float2half(w1[i]);
        g_Wt2[n * 64 + k] = __float2half(w2[i]);
    }
}

// ---------------- scalar GEMM (encoder/decoder, fp32): A[n x K] @ W[K x 64] ----------------
template<int K, bool WRITE_SCALED>
__global__ void __launch_bounds__(128) gemm_k(
    const float* __restrict__ A,
    const float* __restrict__ W1,
    const float* __restrict__ b1,
    float* __restrict__ O1,
    __half* __restrict__ Osh)
{
    __shared__ float AsT[64][36];
    __shared__ float Ws[64 * 64];

    int tid = threadIdx.x;
    int tx = tid & 15;
    int ty = tid >> 4;
    int rowbase = blockIdx.x * 32;
    int col0 = tx * 4;

    float acc1[4][4] = {};

    #pragma unroll
    for (int c = 0; c < K / 64; c++) {
        #pragma unroll
        for (int it = 0; it < 4; it++) {
            int i = tid + it * 128;
            int r = i >> 4, q = i & 15;
            int row = rowbase + r;
            float4 v = make_float4(0.f, 0.f, 0.f, 0.f);
            if (row < NN)
                v = *(const float4*)&A[(size_t)row * K + c * 64 + q * 4];
            AsT[q * 4 + 0][r] = v.x; AsT[q * 4 + 1][r] = v.y;
            AsT[q * 4 + 2][r] = v.z; AsT[q * 4 + 3][r] = v.w;
        }
        #pragma unroll
        for (int i = tid; i < 64 * 16; i += 128)
            ((float4*)Ws)[i] = ((const float4*)(W1 + c * 64 * 64))[i];
        __syncthreads();

        #pragma unroll 16
        for (int kk = 0; kk < 64; kk++) {
            float4 av = *(const float4*)&AsT[kk][ty * 4];
            float4 w1 = *(const float4*)&Ws[kk * 64 + col0];
            float a[4] = {av.x, av.y, av.z, av.w};
            #pragma unroll
            for (int i = 0; i < 4; i++) {
                acc1[i][0] += a[i] * w1.x;
                acc1[i][1] += a[i] * w1.y;
                acc1[i][2] += a[i] * w1.z;
                acc1[i][3] += a[i] * w1.w;
            }
        }
        __syncthreads();
    }

    float4 bb1 = *(const float4*)&b1[col0];
    #pragma unroll
    for (int i = 0; i < 4; i++) {
        int row = rowbase + ty * 4 + i;
        if (row >= NN) break;
        float4 o;
        o.x = fmaxf(acc1[i][0] + bb1.x, 0.f);
        o.y = fmaxf(acc1[i][1] + bb1.y, 0.f);
        o.z = fmaxf(acc1[i][2] + bb1.z, 0.f);
        o.w = fmaxf(acc1[i][3] + bb1.w, 0.f);
        *(float4*)&O1[(size_t)row * 64 + col0] = o;
        if (WRITE_SCALED) {
            float s = g_dis[row];
            float4 os = make_float4(s * o.x, s * o.y, s * o.z, s * o.w);
            *(uint2*)&Osh[(size_t)row * 64 + col0] = f4_to_h4(os);
        }
    }
}

// ---------------- tensor-core dual GEMM: AH[n x 64] fp16 @ {Wt1,Wt2} ----------------
__global__ void __launch_bounds__(128) k_mma_dual(
    const float* __restrict__ b1v, const float* __restrict__ b2v)
{
    __shared__ __half As [64 * 72];
    __shared__ __half B1s[64 * 72];
    __shared__ __half B2s[64 * 72];

    int tid = threadIdx.x;
    int rowbase = blockIdx.x * 64;

    #pragma unroll
    for (int it = 0; it < 8; it++) {
        int i = tid + it * 128;
        int r = i >> 4;
        int c4 = (i & 15) * 4;
        int row = rowbase + r;
        uint2 v = make_uint2(0u, 0u);
        if (row < NN) v = *(const uint2*)&g_AH[(size_t)row * 64 + c4];
        *(uint2*)&As[r * 72 + c4] = v;
    }
    #pragma unroll
    for (int it = 0; it < 8; it++) {
        int i = tid + it * 128;
        int n = i >> 4;
        int c4 = (i & 15) * 4;
        *(uint2*)&B1s[n * 72 + c4] = *(const uint2*)&g_Wt1[n * 64 + c4];
        *(uint2*)&B2s[n * 72 + c4] = *(const uint2*)&g_Wt2[n * 64 + c4];
    }
    __syncthreads();

    int w = tid >> 5, lane = tid & 31;
    int g = lane >> 2, tig = lane & 3;
    int m0 = w * 16;

    float c1[8][4], c2[8][4];
    #pragma unroll
    for (int nc = 0; nc < 8; nc++)
        #pragma unroll
        for (int q = 0; q < 4; q++) { c1[nc][q] = 0.f; c2[nc][q] = 0.f; }

    #pragma unroll
    for (int kc = 0; kc < 4; kc++) {
        int k0 = kc * 16 + tig * 2;
        unsigned a0 = *(const unsigned*)&As[(m0 + g    ) * 72 + k0];
        unsigned a1 = *(const unsigned*)&As[(m0 + g + 8) * 72 + k0];
        unsigned a2 = *(const unsigned*)&As[(m0 + g    ) * 72 + k0 + 8];
        unsigned a3 = *(const unsigned*)&As[(m0 + g + 8) * 72 + k0 + 8];
        #pragma unroll
        for (int nc = 0; nc < 8; nc++) {
            int nr = nc * 8 + g;
            unsigned p0 = *(const unsigned*)&B1s[nr * 72 + k0];
            unsigned p1 = *(const unsigned*)&B1s[nr * 72 + k0 + 8];
            mma16816(c1[nc], a0, a1, a2, a3, p0, p1);
            unsigned q0 = *(const unsigned*)&B2s[nr * 72 + k0];
            unsigned q1 = *(const unsigned*)&B2s[nr * 72 + k0 + 8];
            mma16816(c2[nc], a0, a1, a2, a3, q0, q1);
        }
    }

    int row_lo = rowbase + m0 + g;
    int row_hi = row_lo + 8;
    #pragma unroll
    for (int nc = 0; nc < 8; nc++) {
        int col = nc * 8 + tig * 2;
        float2 bb1 = *(const float2*)&b1v[col];
        float2 bb2 = *(const float2*)&b2v[col];
        if (row_lo < NN) {
            float2 o;
            o.x = fmaxf(c1[nc][0] + bb1.x, 0.f);
            o.y = fmaxf(c1[nc][1] + bb1.y, 0.f);
            *(float2*)&g_Xn[(size_t)row_lo * 64 + col] = o;
            *(__half2*)&g_XGH[(size_t)row_lo * 64 + col] =
                __floats2half2_rn(fmaxf(c2[nc][0] + bb2.x, 0.f),
                                  fmaxf(c2[nc][1] + bb2.y, 0.f));
        }
        if (row_hi < NN) {
            float2 o;
            o.x = fmaxf(c1[nc][2] + bb1.x, 0.f);
            o.y = fmaxf(c1[nc][3] + bb1.y, 0.f);
            *(float2*)&g_Xn[(size_t)row_hi * 64 + col] = o;
            *(__half2*)&g_XGH[(size_t)row_hi * 64 + col] =
                __floats2half2_rn(fmaxf(c2[nc][2] + bb2.x, 0.f),
                                  fmaxf(c2[nc][3] + bb2.y, 0.f));
        }
    }
}

// ---------------- shared aggregation over in-edges (CSR by dst) ----------------
__global__ void __launch_bounds__(256) k_agg()
{
    int g = (blockIdx.x * blockDim.x + threadIdx.x) >> 4;
    int l = threadIdx.x & 15;
    if (g >= NN) return;
    int o = l * 4;

    float4 a = h4_to_f4(*(const uint2*)&g_XdH[(size_t)g * 64 + o]);  // self-loop

    int b = g_rp_dst[g], e = g_rp_dst[g + 1];
    int j = b;
    for (; j + 4 <= e; j += 4) {
        int s0 = g_col_src[j + 0];
        int s1 = g_col_src[j + 1];
        int s2 = g_col_src[j + 2];
        int s3 = g_col_src[j + 3];
        uint2 r0 = *(const uint2*)&g_XdH[(size_t)s0 * 64 + o];
        uint2 r1 = *(const uint2*)&g_XdH[(size_t)s1 * 64 + o];
        uint2 r2 = *(const uint2*)&g_XdH[(size_t)s2 * 64 + o];
        uint2 r3 = *(const uint2*)&g_XdH[(size_t)s3 * 64 + o];
        float4 v0 = h4_to_f4(r0), v1 = h4_to_f4(r1);
        float4 v2 = h4_to_f4(r2), v3 = h4_to_f4(r3);
        a.x += (v0.x + v1.x) + (v2.x + v3.x);
        a.y += (v0.y + v1.y) + (v2.y + v3.y);
        a.z += (v0.z + v1.z) + (v2.z + v3.z);
        a.w += (v0.w + v1.w) + (v2.w + v3.w);
    }
    for (; j < e; j++) {
        int s = g_col_src[j];
        float4 v = h4_to_f4(*(const uint2*)&g_XdH[(size_t)s * 64 + o]);
        a.x += v.x; a.y += v.y; a.z += v.z; a.w += v.w;
    }
    float d = g_dis[g];
    float4 r = make_float4(d * a.x, d * a.y, d * a.z, d * a.w);
    *(uint2*)&g_AH[(size_t)g * 64 + o] = f4_to_h4(r);
}

// ---------------- gate + state update (CSR by src) ----------------
__global__ void __launch_bounds__(256) k_gate()
{
    int g = (blockIdx.x * blockDim.x + threadIdx.x) >> 4;
    int l = threadIdx.x & 15;
    if (g >= NN) return;
    int o = l * 4;

    float4 xs = h4_to_f4(*(const uint2*)&g_XGH[(size_t)g * 64 + o]);
    float4 s = make_float4(0.f, 0.f, 0.f, 0.f);
    int b = g_rp_src[g], e = g_rp_src[g + 1];
    int j = b;
    for (; j + 4 <= e; j += 4) {
        int d0 = g_col_dst[j + 0];
        int d1 = g_col_dst[j + 1];
        int d2 = g_col_dst[j + 2];
        int d3 = g_col_dst[j + 3];
        uint2 r0 = *(const uint2*)&g_XGH[(size_t)d0 * 64 + o];
        uint2 r1 = *(const uint2*)&g_XGH[(size_t)d1 * 64 + o];
        uint2 r2 = *(const uint2*)&g_XGH[(size_t)d2 * 64 + o];
        uint2 r3 = *(const uint2*)&g_XGH[(size_t)d3 * 64 + o];
        float4 v0 = h4_to_f4(r0), v1 = h4_to_f4(r1);
        float4 v2 = h4_to_f4(r2), v3 = h4_to_f4(r3);
        float t;
        t = xs.x - v0.x; s.x += t * t;  t = xs.y - v0.y; s.y += t * t;
        t = xs.z - v0.z; s.z += t * t;  t = xs.w - v0.w; s.w += t * t;
        t = xs.x - v1.x; s.x += t * t;  t = xs.y - v1.y; s.y += t * t;
        t = xs.z - v1.z; s.z += t * t;  t = xs.w - v1.w; s.w += t * t;
        t = xs.x - v2.x; s.x += t * t;  t = xs.y - v2.y; s.y += t * t;
        t = xs.z - v2.z; s.z += t * t;  t = xs.w - v2.w; s.w += t * t;
        t = xs.x - v3.x; s.x += t * t;  t = xs.y - v3.y; s.y += t * t;
        t = xs.z - v3.z; s.z += t * t;  t = xs.w - v3.w; s.w += t * t;
    }
    for (; j < e; j++) {
        int d = g_col_dst[j];
        float4 v = h4_to_f4(*(const uint2*)&g_XGH[(size_t)d * 64 + o]);
        float t;
        t = xs.x - v.x; s.x += t * t;  t = xs.y - v.y; s.y += t * t;
        t = xs.z - v.z; s.z += t * t;  t = xs.w - v.w; s.w += t * t;
    }
    float inv = 1.0f / fmaxf((float)(e - b), 1.f);
    float4 tau;
    tau.x = tanhf(s.x * inv); tau.y = tanhf(s.y * inv);
    tau.z = tanhf(s.z * inv); tau.w = tanhf(s.w * inv);

    float4 xo = *(const float4*)&g_X [(size_t)g * 64 + o];
    float4 xn = *(const float4*)&g_Xn[(size_t)g * 64 + o];
    float4 r;
    r.x = xo.x + tau.x * (xn.x - xo.x);
    r.y = xo.y + tau.y * (xn.y - xo.y);
    r.z = xo.z + tau.z * (xn.z - xo.z);
    r.w = xo.w + tau.w * (xn.w - xo.w);
    *(float4*)&g_X[(size_t)g * 64 + o] = r;
    float di = g_dis[g];
    float4 rd = make_float4(di * r.x, di * r.y, di * r.z, di * r.w);
    *(uint2*)&g_XdH[(size_t)g * 64 + o] = f4_to_h4(rd);
}

// ---------------- launch ----------------
extern "C" void kernel_launch(void* const* d_in, const int* in_sizes, int n_in,
                              void* d_out, int out_size)
{
    const float* x      = (const float*)d_in[0];
    const int*   ei     = (const int*)  d_in[1];
    const float* enc_w  = (const float*)d_in[2];
    const float* enc_b  = (const float*)d_in[3];
    const float* conv_w = (const float*)d_in[4];
    const float* conv_b = (const float*)d_in[5];
    const float* gg_w   = (const float*)d_in[6];
    const float* gg_b   = (const float*)d_in[7];
    const float* dec_w  = (const float*)d_in[8];
    const float* dec_b  = (const float*)d_in[9];
    float* out = (float*)d_out;

    float *pX, *pXn;
    __half *pXdH;
    cudaGetSymbolAddress((void**)&pX,   g_X);
    cudaGetSymbolAddress((void**)&pXdH, g_XdH);
    cudaGetSymbolAddress((void**)&pXn,  g_Xn);

    // graph preprocessing + weight conversion
    k_zero_counts<<<(NN + 255) / 256, 256>>>();
    k_wconv<<<16, 256>>>(conv_w, gg_w);
    k_count<<<(NE + 255) / 256, 256>>>(ei);
    k_blocksum<<<dim3(NBLK, 2), 256>>>();
    k_scan_bsum<<<2, 256>>>();
    k_scatter<<<dim3(NBLK, 2), 256>>>();
    k_fill<<<(NE + 255) / 256, 256>>>(ei);

    const int GEMM_BLOCKS = (NN + 31) / 32;
    const int MMA_BLOCKS  = (NN + 63) / 64;
    const int NODE_BLOCKS = (NN * 16 + 255) / 256;

    // encoder: X = relu(x @ enc_w + enc_b); XdH = half(dis*X)
    gemm_k<256, true><<<GEMM_BLOCKS, 128>>>(x, enc_w, enc_b, pX, pXdH);

    for (int it = 0; it < DEPTH; it++) {
        k_agg<<<NODE_BLOCKS, 256>>>();
        k_mma_dual<<<MMA_BLOCKS, 128>>>(conv_b, gg_b);
        k_gate<<<NODE_BLOCKS, 256>>>();
    }

    // decoder: out = relu(X @ dec_w + dec_b)
    gemm_k<64, false><<<GEMM_BLOCKS, 128>>>(pX, dec_w, dec_b, out, nullptr);
}

// round 7
// speedup vs baseline: 1.7904x; 1.0981x over previous
#include <cuda_runtime.h>
#include <cuda_fp16.h>
#include <math.h>

#define NN 50000
#define NE 800000
#define DEPTH 4
#define NBLK 196   // (NN + 255) / 256

// ---------------- scratch (static device globals; no allocation) ----------------
__device__ float  g_X  [NN*64];   // node state (fp32)
__device__ __half g_XdH[NN*64];   // dis[i]*X[i] as fp16 (gather stream)
__device__ __half g_AH [NN*64];   // aggregated features as fp16 (MMA input)
__device__ float  g_Xn [NN*64];   // relu(conv(X))
__device__ __half g_XGH[NN*64];   // relu(gate-conv(X)) as fp16 (gather stream)
__device__ __half g_Wt1[64*64];   // conv_w transposed fp16: [n][k]
__device__ __half g_Wt2[64*64];   // gg_w transposed fp16: [n][k]
__device__ __half g_WtE[64*256];  // enc_w transposed fp16: [n][k]
__device__ float g_dis[NN];
__device__ int g_cnt_dst[NN];
__device__ int g_cnt_src[NN];
__device__ int g_rp_dst[NN+1];
__device__ int g_rp_src[NN+1];
__device__ int g_off_dst[NN];
__device__ int g_off_src[NN];
__device__ int g_col_src[NE];   // CSR by dst
__device__ int g_col_dst[NE];   // CSR by src
__device__ int g_bsum[2][NBLK];
__device__ int g_bpre[2][NBLK];

// ---------------- helpers ----------------
__device__ __forceinline__ float4 h4_to_f4(uint2 raw) {
    __half2 h0 = *reinterpret_cast<__half2*>(&raw.x);
    __half2 h1 = *reinterpret_cast<__half2*>(&raw.y);
    float2 f0 = __half22float2(h0);
    float2 f1 = __half22float2(h1);
    return make_float4(f0.x, f0.y, f1.x, f1.y);
}
__device__ __forceinline__ uint2 f4_to_h4(float4 v) {
    __half2 h0 = __floats2half2_rn(v.x, v.y);
    __half2 h1 = __floats2half2_rn(v.z, v.w);
    uint2 r;
    r.x = *reinterpret_cast<unsigned*>(&h0);
    r.y = *reinterpret_cast<unsigned*>(&h1);
    return r;
}
__device__ __forceinline__ void mma16816(float c[4],
    unsigned a0, unsigned a1, unsigned a2, unsigned a3,
    unsigned b0, unsigned b1)
{
    asm volatile(
        "mma.sync.aligned.m16n8k16.row.col.f32.f16.f16.f32 "
        "{%0,%1,%2,%3}, {%4,%5,%6,%7}, {%8,%9}, {%0,%1,%2,%3};"
        : "+f"(c[0]), "+f"(c[1]), "+f"(c[2]), "+f"(c[3])
        : "r"(a0), "r"(a1), "r"(a2), "r"(a3), "r"(b0), "r"(b1));
}

// inclusive block scan, 256 threads (8 warps)
__device__ __forceinline__ int block_incl_scan(int v, int* warpsums) {
    int lane = threadIdx.x & 31, wid = threadIdx.x >> 5;
    #pragma unroll
    for (int o = 1; o < 32; o <<= 1) {
        int u = __shfl_up_sync(0xffffffffu, v, o);
        if (lane >= o) v += u;
    }
    if (lane == 31) warpsums[wid] = v;
    __syncthreads();
    if (wid == 0) {
        int s = (lane < 8) ? warpsums[lane] : 0;
        #pragma unroll
        for (int o = 1; o < 8; o <<= 1) {
            int u = __shfl_up_sync(0xffffffffu, s, o);
            if (lane >= o) s += u;
        }
        if (lane < 8) warpsums[lane] = s;
    }
    __syncthreads();
    if (wid > 0) v += warpsums[wid - 1];
    return v;
}

// ---------------- graph preprocessing ----------------
__global__ void k_zero_counts() {
    int i = blockIdx.x * blockDim.x + threadIdx.x;
    if (i < NN) { g_cnt_dst[i] = 0; g_cnt_src[i] = 0; }
}

__global__ void k_count(const int* __restrict__ ei) {
    int i = blockIdx.x * blockDim.x + threadIdx.x;
    if (i < NE) {
        int s = ei[i], d = ei[NE + i];
        atomicAdd(&g_cnt_dst[d], 1);
        atomicAdd(&g_cnt_src[s], 1);
    }
}

__global__ void __launch_bounds__(256) k_blocksum() {
    __shared__ int warpsums[8];
    int arr = blockIdx.y;
    const int* cnt = arr ? g_cnt_src : g_cnt_dst;
    int i = blockIdx.x * 256 + threadIdx.x;
    int v = (i < NN) ? cnt[i] : 0;
    int inc = block_incl_scan(v, warpsums);
    if (threadIdx.x == 255) g_bsum[arr][blockIdx.x] = inc;
}

__global__ void __launch_bounds__(256) k_scan_bsum() {
    __shared__ int warpsums[8];
    int arr = blockIdx.x;
    int t = threadIdx.x;
    int v = (t < NBLK) ? g_bsum[arr][t] : 0;
    int inc = block_incl_scan(v, warpsums);
    if (t < NBLK) g_bpre[arr][t] = inc - v;   // exclusive
}

__global__ void __launch_bounds__(256) k_scatter() {
    __shared__ int warpsums[8];
    int arr = blockIdx.y;
    const int* cnt = arr ? g_cnt_src : g_cnt_dst;
    int* rp  = arr ? g_rp_src  : g_rp_dst;
    int* off = arr ? g_off_src : g_off_dst;
    int i = blockIdx.x * 256 + threadIdx.x;
    int v = (i < NN) ? cnt[i] : 0;
    int inc = block_incl_scan(v, warpsums);
    int base = g_bpre[arr][blockIdx.x];
    if (i < NN) {
        int ex = base + inc - v;
        rp[i] = ex; off[i] = ex;
        if (arr == 0) g_dis[i] = rsqrtf((float)v + 1.0f);
        if (i == NN - 1) rp[NN] = base + inc;
    }
}

__global__ void k_fill(const int* __restrict__ ei) {
    int i = blockIdx.x * blockDim.x + threadIdx.x;
    if (i < NE) {
        int s = ei[i], d = ei[NE + i];
        int p = atomicAdd(&g_off_dst[d], 1); g_col_src[p] = s;
        int q = atomicAdd(&g_off_src[s], 1); g_col_dst[q] = d;
    }
}

// ---------------- weight conversion ----------------
// conv_w/gg_w: fp32 [k][n] (64x64) -> fp16 [n][k];  enc_w: fp32 [k][n] (256x64) -> fp16 [n*256+k]
__global__ void k_wconv(const float* __restrict__ w1, const float* __restrict__ w2,
                        const float* __restrict__ we) {
    int i = blockIdx.x * blockDim.x + threadIdx.x;
    if (i < 4096) {
        int k = i >> 6, n = i & 63;
        g_Wt1[n * 64 + k] = __float2half(w1[i]);
        g_Wt2[n * 64 + k] = __float2half(w2[i]);
    }
    if (i < 16384) {
        int k = i >> 6, n = i & 63;
        g_WtE[n * 256 + k] = __float2half(we[i]);
    }
}

// ---------------- scalar GEMM (decoder, fp32): A[n x 64] @ W[64 x 64] ----------------
__global__ void __launch_bounds__(128) gemm_dec(
    const float* __restrict__ A,
    const float* __restrict__ W1,
    const float* __restrict__ b1,
    float* __restrict__ O1)
{
    __shared__ float AsT[64][36];
    __shared__ float Ws[64 * 64];

    int tid = threadIdx.x;
    int tx = tid & 15;
    int ty = tid >> 4;
    int rowbase = blockIdx.x * 32;
    int col0 = tx * 4;

    float acc1[4][4] = {};

    #pragma unroll
    for (int it = 0; it < 4; it++) {
        int i = tid + it * 128;
        int r = i >> 4, q = i & 15;
        int row = rowbase + r;
        float4 v = make_float4(0.f, 0.f, 0.f, 0.f);
        if (row < NN)
            v = *(const float4*)&A[(size_t)row * 64 + q * 4];
        AsT[q * 4 + 0][r] = v.x; AsT[q * 4 + 1][r] = v.y;
        AsT[q * 4 + 2][r] = v.z; AsT[q * 4 + 3][r] = v.w;
    }
    #pragma unroll
    for (int i = tid; i < 64 * 16; i += 128)
        ((float4*)Ws)[i] = ((const float4*)W1)[i];
    __syncthreads();

    #pragma unroll 16
    for (int kk = 0; kk < 64; kk++) {
        float4 av = *(const float4*)&AsT[kk][ty * 4];
        float4 w1 = *(const float4*)&Ws[kk * 64 + col0];
        float a[4] = {av.x, av.y, av.z, av.w};
        #pragma unroll
        for (int i = 0; i < 4; i++) {
            acc1[i][0] += a[i] * w1.x;
            acc1[i][1] += a[i] * w1.y;
            acc1[i][2] += a[i] * w1.z;
            acc1[i][3] += a[i] * w1.w;
        }
    }

    float4 bb1 = *(const float4*)&b1[col0];
    #pragma unroll
    for (int i = 0; i < 4; i++) {
        int row = rowbase + ty * 4 + i;
        if (row >= NN) break;
        float4 o;
        o.x = fmaxf(acc1[i][0] + bb1.x, 0.f);
        o.y = fmaxf(acc1[i][1] + bb1.y, 0.f);
        o.z = fmaxf(acc1[i][2] + bb1.z, 0.f);
        o.w = fmaxf(acc1[i][3] + bb1.w, 0.f);
        *(float4*)&O1[(size_t)row * 64 + col0] = o;
    }
}

// ---------------- tensor-core encoder: x[n x 256] fp32 -> fp16 @ WtE ----------------
// X = relu(x@enc_w + enc_b) fp32;  XdH = half(dis * X)
__global__ void __launch_bounds__(128) k_mma_enc(
    const float* __restrict__ x, const float* __restrict__ b1v)
{
    __shared__ __half As[64 * 72];
    __shared__ __half Bs[64 * 72];

    int tid = threadIdx.x;
    int rowbase = blockIdx.x * 64;
    int w = tid >> 5, lane = tid & 31;
    int g = lane >> 2, tig = lane & 3;
    int m0 = w * 16;

    float c1[8][4];
    #pragma unroll
    for (int nc = 0; nc < 8; nc++)
        #pragma unroll
        for (int q = 0; q < 4; q++) c1[nc][q] = 0.f;

    for (int c = 0; c < 4; c++) {        // K chunks of 64
        // A chunk: 64 rows x 64 cols fp32 -> fp16 smem
        #pragma unroll
        for (int it = 0; it < 8; it++) {
            int i = tid + it * 128;       // one float4 each
            int r = i >> 4;
            int c4 = (i & 15) * 4;
            int row = rowbase + r;
            float4 v = make_float4(0.f, 0.f, 0.f, 0.f);
            if (row < NN)
                v = *(const float4*)&x[(size_t)row * 256 + c * 64 + c4];
            *(uint2*)&As[r * 72 + c4] = f4_to_h4(v);
        }
        // B chunk: WtE[n][c*64 + k], 64 x 64 fp16
        #pragma unroll
        for (int it = 0; it < 8; it++) {
            int i = tid + it * 128;
            int n = i >> 4;
            int c4 = (i & 15) * 4;
            *(uint2*)&Bs[n * 72 + c4] = *(const uint2*)&g_WtE[n * 256 + c * 64 + c4];
        }
        __syncthreads();

        #pragma unroll
        for (int kc = 0; kc < 4; kc++) {
            int k0 = kc * 16 + tig * 2;
            unsigned a0 = *(const unsigned*)&As[(m0 + g    ) * 72 + k0];
            unsigned a1 = *(const unsigned*)&As[(m0 + g + 8) * 72 + k0];
            unsigned a2 = *(const unsigned*)&As[(m0 + g    ) * 72 + k0 + 8];
            unsigned a3 = *(const unsigned*)&As[(m0 + g + 8) * 72 + k0 + 8];
            #pragma unroll
            for (int nc = 0; nc < 8; nc++) {
                int nr = nc * 8 + g;
                unsigned p0 = *(const unsigned*)&Bs[nr * 72 + k0];
                unsigned p1 = *(const unsigned*)&Bs[nr * 72 + k0 + 8];
                mma16816(c1[nc], a0, a1, a2, a3, p0, p1);
            }
        }
        __syncthreads();
    }

    int row_lo = rowbase + m0 + g;
    int row_hi = row_lo + 8;
    float dlo = (row_lo < NN) ? g_dis[row_lo] : 0.f;
    float dhi = (row_hi < NN) ? g_dis[row_hi] : 0.f;
    #pragma unroll
    for (int nc = 0; nc < 8; nc++) {
        int col = nc * 8 + tig * 2;
        float2 bb1 = *(const float2*)&b1v[col];
        if (row_lo < NN) {
            float2 o;
            o.x = fmaxf(c1[nc][0] + bb1.x, 0.f);
            o.y = fmaxf(c1[nc][1] + bb1.y, 0.f);
            *(float2*)&g_X[(size_t)row_lo * 64 + col] = o;
            *(__half2*)&g_XdH[(size_t)row_lo * 64 + col] =
                __floats2half2_rn(dlo * o.x, dlo * o.y);
        }
        if (row_hi < NN) {
            float2 o;
            o.x = fmaxf(c1[nc][2] + bb1.x, 0.f);
            o.y = fmaxf(c1[nc][3] + bb1.y, 0.f);
            *(float2*)&g_X[(size_t)row_hi * 64 + col] = o;
            *(__half2*)&g_XdH[(size_t)row_hi * 64 + col] =
                __floats2half2_rn(dhi * o.x, dhi * o.y);
        }
    }
}

// ---------------- tensor-core dual GEMM: AH[n x 64] fp16 @ {Wt1,Wt2} ----------------
__global__ void __launch_bounds__(128) k_mma_dual(
    const float* __restrict__ b1v, const float* __restrict__ b2v)
{
    __shared__ __half As [64 * 72];
    __shared__ __half B1s[64 * 72];
    __shared__ __half B2s[64 * 72];

    int tid = threadIdx.x;
    int rowbase = blockIdx.x * 64;

    #pragma unroll
    for (int it = 0; it < 8; it++) {
        int i = tid + it * 128;
        int r = i >> 4;
        int c4 = (i & 15) * 4;
        int row = rowbase + r;
        uint2 v = make_uint2(0u, 0u);
        if (row < NN) v = *(const uint2*)&g_AH[(size_t)row * 64 + c4];
        *(uint2*)&As[r * 72 + c4] = v;
    }
    #pragma unroll
    for (int it = 0; it < 8; it++) {
        int i = tid + it * 128;
        int n = i >> 4;
        int c4 = (i & 15) * 4;
        *(uint2*)&B1s[n * 72 + c4] = *(const uint2*)&g_Wt1[n * 64 + c4];
        *(uint2*)&B2s[n * 72 + c4] = *(const uint2*)&g_Wt2[n * 64 + c4];
    }
    __syncthreads();

    int w = tid >> 5, lane = tid & 31;
    int g = lane >> 2, tig = lane & 3;
    int m0 = w * 16;

    float c1[8][4], c2[8][4];
    #pragma unroll
    for (int nc = 0; nc < 8; nc++)
        #pragma unroll
        for (int q = 0; q < 4; q++) { c1[nc][q] = 0.f; c2[nc][q] = 0.f; }

    #pragma unroll
    for (int kc = 0; kc < 4; kc++) {
        int k0 = kc * 16 + tig * 2;
        unsigned a0 = *(const unsigned*)&As[(m0 + g    ) * 72 + k0];
        unsigned a1 = *(const unsigned*)&As[(m0 + g + 8) * 72 + k0];
        unsigned a2 = *(const unsigned*)&As[(m0 + g    ) * 72 + k0 + 8];
        unsigned a3 = *(const unsigned*)&As[(m0 + g + 8) * 72 + k0 + 8];
        #pragma unroll
        for (int nc = 0; nc < 8; nc++) {
            int nr = nc * 8 + g;
            unsigned p0 = *(const unsigned*)&B1s[nr * 72 + k0];
            unsigned p1 = *(const unsigned*)&B1s[nr * 72 + k0 + 8];
            mma16816(c1[nc], a0, a1, a2, a3, p0, p1);
            unsigned q0 = *(const unsigned*)&B2s[nr * 72 + k0];
            unsigned q1 = *(const unsigned*)&B2s[nr * 72 + k0 + 8];
            mma16816(c2[nc], a0, a1, a2, a3, q0, q1);
        }
    }

    int row_lo = rowbase + m0 + g;
    int row_hi = row_lo + 8;
    #pragma unroll
    for (int nc = 0; nc < 8; nc++) {
        int col = nc * 8 + tig * 2;
        float2 bb1 = *(const float2*)&b1v[col];
        float2 bb2 = *(const float2*)&b2v[col];
        if (row_lo < NN) {
            float2 o;
            o.x = fmaxf(c1[nc][0] + bb1.x, 0.f);
            o.y = fmaxf(c1[nc][1] + bb1.y, 0.f);
            *(float2*)&g_Xn[(size_t)row_lo * 64 + col] = o;
            *(__half2*)&g_XGH[(size_t)row_lo * 64 + col] =
                __floats2half2_rn(fmaxf(c2[nc][0] + bb2.x, 0.f),
                                  fmaxf(c2[nc][1] + bb2.y, 0.f));
        }
        if (row_hi < NN) {
            float2 o;
            o.x = fmaxf(c1[nc][2] + bb1.x, 0.f);
            o.y = fmaxf(c1[nc][3] + bb1.y, 0.f);
            *(float2*)&g_Xn[(size_t)row_hi * 64 + col] = o;
            *(__half2*)&g_XGH[(size_t)row_hi * 64 + col] =
                __floats2half2_rn(fmaxf(c2[nc][2] + bb2.x, 0.f),
                                  fmaxf(c2[nc][3] + bb2.y, 0.f));
        }
    }
}

// ---------------- shared aggregation over in-edges (CSR by dst) ----------------
__global__ void __launch_bounds__(256) k_agg()
{
    int g = (blockIdx.x * blockDim.x + threadIdx.x) >> 4;
    int l = threadIdx.x & 15;
    if (g >= NN) return;
    int o = l * 4;

    float4 a = h4_to_f4(*(const uint2*)&g_XdH[(size_t)g * 64 + o]);  // self-loop

    int b = g_rp_dst[g], e = g_rp_dst[g + 1];
    int j = b;
    for (; j + 4 <= e; j += 4) {
        int s0 = g_col_src[j + 0];
        int s1 = g_col_src[j + 1];
        int s2 = g_col_src[j + 2];
        int s3 = g_col_src[j + 3];
        uint2 r0 = *(const uint2*)&g_XdH[(size_t)s0 * 64 + o];
        uint2 r1 = *(const uint2*)&g_XdH[(size_t)s1 * 64 + o];
        uint2 r2 = *(const uint2*)&g_XdH[(size_t)s2 * 64 + o];
        uint2 r3 = *(const uint2*)&g_XdH[(size_t)s3 * 64 + o];
        float4 v0 = h4_to_f4(r0), v1 = h4_to_f4(r1);
        float4 v2 = h4_to_f4(r2), v3 = h4_to_f4(r3);
        a.x += (v0.x + v1.x) + (v2.x + v3.x);
        a.y += (v0.y + v1.y) + (v2.y + v3.y);
        a.z += (v0.z + v1.z) + (v2.z + v3.z);
        a.w += (v0.w + v1.w) + (v2.w + v3.w);
    }
    for (; j < e; j++) {
        int s = g_col_src[j];
        float4 v = h4_to_f4(*(const uint2*)&g_XdH[(size_t)s * 64 + o]);
        a.x += v.x; a.y += v.y; a.z += v.z; a.w += v.w;
    }
    float d = g_dis[g];
    float4 r = make_float4(d * a.x, d * a.y, d * a.z, d * a.w);
    *(uint2*)&g_AH[(size_t)g * 64 + o] = f4_to_h4(r);
}

// ---------------- gate + state update (CSR by src) ----------------
__global__ void __launch_bounds__(256) k_gate()
{
    int g = (blockIdx.x * blockDim.x + threadIdx.x) >> 4;
    int l = threadIdx.x & 15;
    if (g >= NN) return;
    int o = l * 4;

    float4 xs = h4_to_f4(*(const uint2*)&g_XGH[(size_t)g * 64 + o]);
    float4 s = make_float4(0.f, 0.f, 0.f, 0.f);
    int b = g_rp_src[g], e = g_rp_src[g + 1];
    int j = b;
    for (; j + 4 <= e; j += 4) {
        int d0 = g_col_dst[j + 0];
        int d1 = g_col_dst[j + 1];
        int d2 = g_col_dst[j + 2];
        int d3 = g_col_dst[j + 3];
        uint2 r0 = *(const uint2*)&g_XGH[(size_t)d0 * 64 + o];
        uint2 r1 = *(const uint2*)&g_XGH[(size_t)d1 * 64 + o];
        uint2 r2 = *(const uint2*)&g_XGH[(size_t)d2 * 64 + o];
        uint2 r3 = *(const uint2*)&g_XGH[(size_t)d3 * 64 + o];
        float4 v0 = h4_to_f4(r0), v1 = h4_to_f4(r1);
        float4 v2 = h4_to_f4(r2), v3 = h4_to_f4(r3);
        float t;
        t = xs.x - v0.x; s.x += t * t;  t = xs.y - v0.y; s.y += t * t;
        t = xs.z - v0.z; s.z += t * t;  t = xs.w - v0.w; s.w += t * t;
        t = xs.x - v1.x; s.x += t * t;  t = xs.y - v1.y; s.y += t * t;
        t = xs.z - v1.z; s.z += t * t;  t = xs.w - v1.w; s.w += t * t;
        t = xs.x - v2.x; s.x += t * t;  t = xs.y - v2.y; s.y += t * t;
        t = xs.z - v2.z; s.z += t * t;  t = xs.w - v2.w; s.w += t * t;
        t = xs.x - v3.x; s.x += t * t;  t = xs.y - v3.y; s.y += t * t;
        t = xs.z - v3.z; s.z += t * t;  t = xs.w - v3.w; s.w += t * t;
    }
    for (; j < e; j++) {
        int d = g_col_dst[j];
        float4 v = h4_to_f4(*(const uint2*)&g_XGH[(size_t)d * 64 + o]);
        float t;
        t = xs.x - v.x; s.x += t * t;  t = xs.y - v.y; s.y += t * t;
        t = xs.z - v.z; s.z += t * t;  t = xs.w - v.w; s.w += t * t;
    }
    float inv = 1.0f / fmaxf((float)(e - b), 1.f);
    float4 tau;
    tau.x = tanhf(s.x * inv); tau.y = tanhf(s.y * inv);
    tau.z = tanhf(s.z * inv); tau.w = tanhf(s.w * inv);

    float4 xo = *(const float4*)&g_X [(size_t)g * 64 + o];
    float4 xn = *(const float4*)&g_Xn[(size_t)g * 64 + o];
    float4 r;
    r.x = xo.x + tau.x * (xn.x - xo.x);
    r.y = xo.y + tau.y * (xn.y - xo.y);
    r.z = xo.z + tau.z * (xn.z - xo.z);
    r.w = xo.w + tau.w * (xn.w - xo.w);
    *(float4*)&g_X[(size_t)g * 64 + o] = r;
    float di = g_dis[g];
    float4 rd = make_float4(di * r.x, di * r.y, di * r.z, di * r.w);
    *(uint2*)&g_XdH[(size_t)g * 64 + o] = f4_to_h4(rd);
}

// ---------------- launch ----------------
extern "C" void kernel_launch(void* const* d_in, const int* in_sizes, int n_in,
                              void* d_out, int out_size)
{
    const float* x      = (const float*)d_in[0];
    const int*   ei     = (const int*)  d_in[1];
    const float* enc_w  = (const float*)d_in[2];
    const float* enc_b  = (const float*)d_in[3];
    const float* conv_w = (const float*)d_in[4];
    const float* conv_b = (const float*)d_in[5];
    const float* gg_w   = (const float*)d_in[6];
    const float* gg_b   = (const float*)d_in[7];
    const float* dec_w  = (const float*)d_in[8];
    const float* dec_b  = (const float*)d_in[9];
    float* out = (float*)d_out;

    float *pX;
    cudaGetSymbolAddress((void**)&pX, g_X);

    // graph preprocessing + weight conversion
    k_zero_counts<<<(NN + 255) / 256, 256>>>();
    k_wconv<<<64, 256>>>(conv_w, gg_w, enc_w);
    k_count<<<(NE + 255) / 256, 256>>>(ei);
    k_blocksum<<<dim3(NBLK, 2), 256>>>();
    k_scan_bsum<<<2, 256>>>();
    k_scatter<<<dim3(NBLK, 2), 256>>>();
    k_fill<<<(NE + 255) / 256, 256>>>(ei);

    const int MMA_BLOCKS  = (NN + 63) / 64;
    const int NODE_BLOCKS = (NN * 16 + 255) / 256;
    const int DEC_BLOCKS  = (NN + 31) / 32;

    // encoder (tensor cores): X = relu(x @ enc_w + enc_b); XdH = half(dis*X)
    k_mma_enc<<<MMA_BLOCKS, 128>>>(x, enc_b);

    for (int it = 0; it < DEPTH; it++) {
        k_agg<<<NODE_BLOCKS, 256>>>();
        k_mma_dual<<<MMA_BLOCKS, 128>>>(conv_b, gg_b);
        k_gate<<<NODE_BLOCKS, 256>>>();
    }

    // decoder: out = relu(X @ dec_w + dec_b)
    gemm_dec<<<DEC_BLOCKS, 128>>>(pX, dec_w, dec_b, out);
}